// round 13
// baseline (speedup 1.0000x reference)
#include <cuda_runtime.h>
#include <cuda_bf16.h>
#include <cuda_fp16.h>
#include <math.h>
#include <cstdint>

#define DD 128
#define MAXN 100000
#define MAXE 3200000
#define MAXND (MAXN * DD)

// Scratch (static device globals; allocation is forbidden)
__device__ __half g_h[MAXND];      // GEMM output in fp16 (pre-scaled by dinv[row])
__device__ __half g_agg[MAXND];    // aggregation output fp16 (input to next layer)
__device__ int   g_degi[MAXN];
__device__ float g_dinv[MAXN];
__device__ int   g_incl[MAXN];
__device__ int   g_bsum[128];
__device__ int   g_rowptr[MAXN + 1];
__device__ int   g_cursor[MAXN];
__device__ int   g_csr[MAXE];
__device__ float g_colsum[DD];
__device__ float g_sumsq[1];
__device__ float g_mu[DD];
__device__ float g_inv[1];
__device__ unsigned g_done;        // last-block-done counter (zero-initialized)

// ---------------------------------------------------------------------------
__global__ void k_deg_count(const int* __restrict__ dst, int* deg, int E) {
    int e = blockIdx.x * blockDim.x + threadIdx.x;
    if (e < E) atomicAdd(&deg[dst[e]], 1);
}

__global__ void k_dinv(const int* __restrict__ deg, float* dinv, int N) {
    int i = blockIdx.x * blockDim.x + threadIdx.x;
    if (i < N) dinv[i] = rsqrtf((float)(deg[i] + 1));  // +1 self-loop
}

__global__ void k_scan1(const int* __restrict__ deg, int* incl, int* bsum, int N) {
    __shared__ int sh[1024];
    int i = blockIdx.x * 1024 + threadIdx.x;
    int v = (i < N) ? deg[i] : 0;
    sh[threadIdx.x] = v;
    __syncthreads();
    for (int o = 1; o < 1024; o <<= 1) {
        int t = (threadIdx.x >= o) ? sh[threadIdx.x - o] : 0;
        __syncthreads();
        sh[threadIdx.x] += t;
        __syncthreads();
    }
    if (i < N) incl[i] = sh[threadIdx.x];
    if (threadIdx.x == 1023) bsum[blockIdx.x] = sh[1023];
}

__global__ void k_scan2(int* bsum, int nb) {
    __shared__ int sh[128];
    int t = threadIdx.x;
    int v = (t < nb) ? bsum[t] : 0;
    sh[t] = v;
    __syncthreads();
    for (int o = 1; o < 128; o <<= 1) {
        int u = (t >= o) ? sh[t - o] : 0;
        __syncthreads();
        sh[t] += u;
        __syncthreads();
    }
    if (t < nb) bsum[t] = sh[t] - v;  // exclusive
}

__global__ void k_scan3(const int* __restrict__ deg, const int* __restrict__ incl,
                        const int* __restrict__ bsum, int* rowptr, int* cursor, int N) {
    int i = blockIdx.x * blockDim.x + threadIdx.x;
    if (i < N) {
        int dg = deg[i];
        int ex = incl[i] - dg + bsum[i >> 10];
        rowptr[i] = ex;
        cursor[i] = ex;
        if (i == N - 1) rowptr[N] = ex + dg;
    }
}

__global__ void k_scatter(const int* __restrict__ src, const int* __restrict__ dst,
                          int* cursor, int* csr, int E) {
    int e = blockIdx.x * blockDim.x + threadIdx.x;
    if (e < E) {
        int pos = atomicAdd(&cursor[dst[e]], 1);
        csr[pos] = src[e];
    }
}

// ---------------------------------------------------------------------------
// Tensor-core GEMM: H[N,128] = f(X)[N,128] @ W[128,128] * dinv[row], fp16 out.
// bf16 3-product split, fp32 accumulation. ldmatrix fragment loads.
#define W_STRIDE 136
#define X_STRIDE 24

__device__ __forceinline__ uint32_t smem_u32(const void* p) {
    uint32_t a;
    asm("{.reg .u64 t; cvta.to.shared.u64 t, %1; cvt.u32.u64 %0, t;}" : "=r"(a) : "l"(p));
    return a;
}

__device__ __forceinline__ void ldsm_x4(unsigned* r, uint32_t addr) {
    asm volatile("ldmatrix.sync.aligned.m8n8.x4.shared.b16 {%0,%1,%2,%3}, [%4];"
                 : "=r"(r[0]), "=r"(r[1]), "=r"(r[2]), "=r"(r[3]) : "r"(addr));
}
__device__ __forceinline__ void ldsm_x2(unsigned* r, uint32_t addr) {
    asm volatile("ldmatrix.sync.aligned.m8n8.x2.shared.b16 {%0,%1}, [%2];"
                 : "=r"(r[0]), "=r"(r[1]) : "r"(addr));
}

__device__ __forceinline__ void load8(const float* p, float* v) {
    float4 a = *(const float4*)p;
    float4 b = *(const float4*)(p + 4);
    v[0] = a.x; v[1] = a.y; v[2] = a.z; v[3] = a.w;
    v[4] = b.x; v[5] = b.y; v[6] = b.z; v[7] = b.w;
}
__device__ __forceinline__ void load8(const __half* p, float* v) {
    uint4 u = *(const uint4*)p;
    const __half2* h = reinterpret_cast<const __half2*>(&u);
#pragma unroll
    for (int i = 0; i < 4; i++) {
        float2 f = __half22float2(h[i]);
        v[2 * i] = f.x;
        v[2 * i + 1] = f.y;
    }
}

__device__ __forceinline__ void mma16816(float* c, const unsigned* a, const unsigned* b) {
    asm volatile(
        "mma.sync.aligned.m16n8k16.row.col.f32.bf16.bf16.f32 "
        "{%0,%1,%2,%3},{%4,%5,%6,%7},{%8,%9},{%0,%1,%2,%3};"
        : "+f"(c[0]), "+f"(c[1]), "+f"(c[2]), "+f"(c[3])
        : "r"(a[0]), "r"(a[1]), "r"(a[2]), "r"(a[3]), "r"(b[0]), "r"(b[1]));
}

template <typename IT>
__global__ void __launch_bounds__(256, 2)
k_gemm_tc(const IT* __restrict__ X, const float* __restrict__ W,
          __half* __restrict__ H, const float* __restrict__ mu,
          const float* __restrict__ invp, const float* __restrict__ dinv,
          int applyNorm, int N) {
    extern __shared__ __nv_bfloat16 smem[];
    __nv_bfloat16* wh = smem;                       // [128][W_STRIDE]
    __nv_bfloat16* wl = wh + 128 * W_STRIDE;
    __nv_bfloat16* xh = wl + 128 * W_STRIDE;        // [128][X_STRIDE]
    __nv_bfloat16* xl = xh + 128 * X_STRIDE;

    const int tid = threadIdx.x;
    const int warp = tid >> 5;
    const int lane = tid & 31;
    const int g = lane >> 2;
    const int tg = lane & 3;
    const int row0 = blockIdx.x * 128;
    const float inv = applyNorm ? invp[0] : 0.0f;

    // Stage W (hi + lo), transposed to [n][k]
    for (int i = tid; i < DD * DD; i += 256) {
        int k = i >> 7, n = i & 127;
        float w = W[i];
        __nv_bfloat16 hi = __float2bfloat16(w);
        float lo = w - __bfloat162float(hi);
        wh[n * W_STRIDE + k] = hi;
        wl[n * W_STRIDE + k] = __float2bfloat16(lo);
    }

    float c[16][4];
#pragma unroll
    for (int i = 0; i < 16; i++)
#pragma unroll
        for (int j = 0; j < 4; j++) c[i][j] = 0.0f;

    const int arow = warp * 16;
    const int sr = tid >> 1;            // staging row 0..127
    const int sc8 = (tid & 1) << 3;     // staging col 0 or 8
    const int gr = row0 + sr;
    const bool valid = (gr < N);
    const IT* xrow = X + ((size_t)gr << 7) + sc8;   // + ch*16 per chunk

    // ldmatrix lane addressing
    const int l8 = ((lane >> 3) & 1) * 8;
    const int l16 = ((lane >> 4) & 1) * 8;
    const int arow_l = arow + l8 + (lane & 7);
    const uint32_t xh_u32 = smem_u32(xh);
    const uint32_t a_off = (uint32_t)(arow_l * X_STRIDE + l16) * 2;
    const uint32_t a_lo = (uint32_t)(128 * X_STRIDE) * 2;
    const uint32_t wh_u32 = smem_u32(wh);
    const uint32_t b_lane_off = (uint32_t)((lane & 7) * W_STRIDE + l8) * 2;
    const uint32_t b_lo = (uint32_t)(128 * W_STRIDE) * 2;

    float v[8];
    if (valid) load8(xrow, v);
    else {
#pragma unroll
        for (int q = 0; q < 8; q++) v[q] = 0.0f;
    }

    for (int ch = 0; ch < 8; ch++) {
        float sv[8];
        if (valid && applyNorm) {
#pragma unroll
            for (int q = 0; q < 8; q++)
                sv[q] = fmaxf((v[q] - __ldg(&mu[ch * 16 + sc8 + q])) * inv, 0.0f);
        } else {
#pragma unroll
            for (int q = 0; q < 8; q++) sv[q] = v[q];
        }
        __syncthreads();
        {
            __nv_bfloat16 hi8[8], lo8[8];
#pragma unroll
            for (int q = 0; q < 8; q++) {
                hi8[q] = __float2bfloat16(sv[q]);
                lo8[q] = __float2bfloat16(sv[q] - __bfloat162float(hi8[q]));
            }
            *(uint4*)(xh + sr * X_STRIDE + sc8) = *(uint4*)hi8;
            *(uint4*)(xl + sr * X_STRIDE + sc8) = *(uint4*)lo8;
        }
        __syncthreads();

        if (ch < 7) {
            if (valid) load8(xrow + (ch + 1) * 16, v);
        }

        unsigned ah[4], al[4];
        ldsm_x4(ah, xh_u32 + a_off);
        ldsm_x4(al, xh_u32 + a_off + a_lo);

        const int kc = ch * 16;
        const uint32_t bbase = wh_u32 + b_lane_off + (uint32_t)kc * 2;
#pragma unroll
        for (int nt = 0; nt < 16; nt++) {
            unsigned bh[2], bl[2];
            const uint32_t baddr = bbase + (uint32_t)(nt * 8 * W_STRIDE) * 2;
            ldsm_x2(bh, baddr);
            ldsm_x2(bl, baddr + b_lo);
            mma16816(c[nt], ah, bh);
            mma16816(c[nt], ah, bl);
            mma16816(c[nt], al, bh);
        }
    }

    // Epilogue: scale by dinv[row], store half2
    const int r0 = row0 + arow + g;
    const int r1 = r0 + 8;
    const float dv0 = (r0 < N) ? dinv[r0] : 0.0f;
    const float dv1 = (r1 < N) ? dinv[r1] : 0.0f;
#pragma unroll
    for (int nt = 0; nt < 16; nt++) {
        int col = nt * 8 + 2 * tg;
        if (r0 < N)
            *(__half2*)(H + ((size_t)r0 << 7) + col) =
                __floats2half2_rn(c[nt][0] * dv0, c[nt][1] * dv0);
        if (r1 < N)
            *(__half2*)(H + ((size_t)r1 << 7) + col) =
                __floats2half2_rn(c[nt][2] * dv1, c[nt][3] * dv1);
    }
}

// ---------------------------------------------------------------------------
// CSR gather aggregation: 2 rows per warp-load, 16 neighbors in flight.
// STATS path fuses the PairNorm finalize via last-block-done pattern.
__device__ __forceinline__ void add8(float* a, uint4 u) {
    __half2* p = reinterpret_cast<__half2*>(&u);
#pragma unroll
    for (int i = 0; i < 4; i++) {
        float2 f = __half22float2(p[i]);
        a[2 * i] += f.x;
        a[2 * i + 1] += f.y;
    }
}

template <typename OT, bool HASBIAS, bool STATS>
__global__ void k_aggregate(const __half* __restrict__ h, const int* __restrict__ rowptr,
                            const int* __restrict__ csr, const float* __restrict__ dinv,
                            OT* __restrict__ out, const float* __restrict__ bias,
                            float* colsum, float* sumsq, float* mu, float* invp, int N) {
    __shared__ float s_col[DD];
    __shared__ float s_ss;
    if (STATS) {
        if (threadIdx.x < DD) s_col[threadIdx.x] = 0.0f;
        if (threadIdx.x == 0) s_ss = 0.0f;
        __syncthreads();
    }
    const int lane = threadIdx.x & 31;
    const int half = lane >> 4;
    const int cpos = lane & 15;
    const int warp = (blockIdx.x * blockDim.x + threadIdx.x) >> 5;
    const int nwarps = (gridDim.x * blockDim.x) >> 5;
    const uint4* hp = reinterpret_cast<const uint4*>(h);  // row stride 16 uint4

    float cs[8];
    float ssacc = 0.0f;
    if (STATS) {
#pragma unroll
        for (int i = 0; i < 8; i++) cs[i] = 0.0f;
    }

    for (int d = warp; d < N; d += nwarps) {
        float a[8];
#pragma unroll
        for (int i = 0; i < 8; i++) a[i] = 0.0f;

        if (half == 0) add8(a, __ldg(&hp[((size_t)d << 4) + cpos]));  // self

        int j = __ldg(&rowptr[d]);
        const int je = __ldg(&rowptr[d + 1]);
        // 16 neighbors per iteration: 8 paired loads in flight
        for (; j + 16 <= je; j += 16) {
            int s0 = __ldg(&csr[j + 0 + half]);
            int s1 = __ldg(&csr[j + 2 + half]);
            int s2 = __ldg(&csr[j + 4 + half]);
            int s3 = __ldg(&csr[j + 6 + half]);
            int s4 = __ldg(&csr[j + 8 + half]);
            int s5 = __ldg(&csr[j + 10 + half]);
            int s6 = __ldg(&csr[j + 12 + half]);
            int s7 = __ldg(&csr[j + 14 + half]);
            uint4 u0 = __ldg(&hp[((size_t)s0 << 4) + cpos]);
            uint4 u1 = __ldg(&hp[((size_t)s1 << 4) + cpos]);
            uint4 u2 = __ldg(&hp[((size_t)s2 << 4) + cpos]);
            uint4 u3 = __ldg(&hp[((size_t)s3 << 4) + cpos]);
            uint4 u4 = __ldg(&hp[((size_t)s4 << 4) + cpos]);
            uint4 u5 = __ldg(&hp[((size_t)s5 << 4) + cpos]);
            uint4 u6 = __ldg(&hp[((size_t)s6 << 4) + cpos]);
            uint4 u7 = __ldg(&hp[((size_t)s7 << 4) + cpos]);
            add8(a, u0); add8(a, u1); add8(a, u2); add8(a, u3);
            add8(a, u4); add8(a, u5); add8(a, u6); add8(a, u7);
        }
        for (; j + 8 <= je; j += 8) {
            int s0 = __ldg(&csr[j + 0 + half]);
            int s1 = __ldg(&csr[j + 2 + half]);
            int s2 = __ldg(&csr[j + 4 + half]);
            int s3 = __ldg(&csr[j + 6 + half]);
            uint4 u0 = __ldg(&hp[((size_t)s0 << 4) + cpos]);
            uint4 u1 = __ldg(&hp[((size_t)s1 << 4) + cpos]);
            uint4 u2 = __ldg(&hp[((size_t)s2 << 4) + cpos]);
            uint4 u3 = __ldg(&hp[((size_t)s3 << 4) + cpos]);
            add8(a, u0); add8(a, u1); add8(a, u2); add8(a, u3);
        }
        for (; j + 2 <= je; j += 2) {
            int s = __ldg(&csr[j + half]);
            add8(a, __ldg(&hp[((size_t)s << 4) + cpos]));
        }
        if (j < je && half == 0) {
            int s = __ldg(&csr[j]);
            add8(a, __ldg(&hp[((size_t)s << 4) + cpos]));
        }

#pragma unroll
        for (int i = 0; i < 8; i++)
            a[i] += __shfl_xor_sync(0xffffffffu, a[i], 16);

        const float sc = __ldg(&dinv[d]);
        float o[8];
#pragma unroll
        for (int i = 0; i < 8; i++) o[i] = a[i] * sc;

        if (HASBIAS) {
            const float4 b = reinterpret_cast<const float4*>(bias)[cpos * 2 + half];
            float4 v = make_float4(o[half * 4 + 0] + b.x, o[half * 4 + 1] + b.y,
                                   o[half * 4 + 2] + b.z, o[half * 4 + 3] + b.w);
            *reinterpret_cast<float4*>(
                reinterpret_cast<float*>(out) + ((size_t)d << 7) + cpos * 8 + half * 4) = v;
        } else {
            __half2 v0 = __floats2half2_rn(o[half * 4 + 0], o[half * 4 + 1]);
            __half2 v1 = __floats2half2_rn(o[half * 4 + 2], o[half * 4 + 3]);
            uint2 pk;
            pk.x = *reinterpret_cast<unsigned*>(&v0);
            pk.y = *reinterpret_cast<unsigned*>(&v1);
            *reinterpret_cast<uint2*>(
                reinterpret_cast<__half*>(out) + ((size_t)d << 7) + cpos * 8 + half * 4) = pk;
        }

        if (STATS && half == 0) {
#pragma unroll
            for (int i = 0; i < 8; i++) {
                cs[i] += o[i];
                ssacc += o[i] * o[i];
            }
        }
    }

    if (STATS) {
        if (half == 0) {
#pragma unroll
            for (int i = 0; i < 8; i++) atomicAdd(&s_col[cpos * 8 + i], cs[i]);
        }
        for (int o = 16; o > 0; o >>= 1) ssacc += __shfl_down_sync(0xffffffff, ssacc, o);
        if (lane == 0) atomicAdd(&s_ss, ssacc);
        __syncthreads();
        if (threadIdx.x < DD) atomicAdd(&colsum[threadIdx.x], s_col[threadIdx.x]);
        if (threadIdx.x == 0) atomicAdd(sumsq, s_ss);

        // --- fused finalize: last block computes mu/inv and resets stats ---
        __threadfence();
        __shared__ unsigned rank_sh;
        if (threadIdx.x == 0) rank_sh = atomicAdd(&g_done, 1u);
        __syncthreads();
        if (rank_sh == gridDim.x - 1) {
            __threadfence();
            const int c = threadIdx.x;
            if (c < DD) {
                float m = colsum[c] / (float)N;
                mu[c] = m;
                colsum[c] = 0.0f;
                s_col[c] = m * m;
            }
            __syncthreads();
            for (int o = 64; o > 0; o >>= 1) {
                if (c < o) s_col[c] += s_col[c + o];
                __syncthreads();
            }
            if (c == 0) {
                float var = fmaxf(sumsq[0] / (float)N - s_col[0], 0.0f);
                invp[0] = 1.0f / (sqrtf(var) + 1e-8f);
                sumsq[0] = 0.0f;
                g_done = 0;
            }
        }
    }
}

// ---------------------------------------------------------------------------
__global__ void k_zero_stats(float* colsum, float* sumsq) {
    int i = threadIdx.x;
    if (i < DD) colsum[i] = 0.0f;
    if (i == 0) { sumsq[0] = 0.0f; g_done = 0; }
}

// ---------------------------------------------------------------------------
extern "C" void kernel_launch(void* const* d_in, const int* in_sizes, int n_in,
                              void* d_out, int out_size) {
    const float* x  = (const float*)d_in[0];
    const int* ei   = (const int*)d_in[1];
    const float* W1 = (const float*)d_in[2];
    const float* W2 = (const float*)d_in[4];
    const float* W3 = (const float*)d_in[6];
    const float* b3 = (const float*)d_in[7];
    float* out = (float*)d_out;

    const int N = in_sizes[0] / DD;
    const int E = in_sizes[1] / 2;
    const int* src = ei;
    const int* dst = ei + E;

    float *p_dinv, *p_colsum, *p_sumsq, *p_mu, *p_inv;
    __half *p_h, *p_agg;
    int *p_degi, *p_incl, *p_bsum, *p_rowptr, *p_cursor, *p_csr;
    cudaGetSymbolAddress((void**)&p_h, g_h);
    cudaGetSymbolAddress((void**)&p_agg, g_agg);
    cudaGetSymbolAddress((void**)&p_degi, g_degi);
    cudaGetSymbolAddress((void**)&p_dinv, g_dinv);
    cudaGetSymbolAddress((void**)&p_incl, g_incl);
    cudaGetSymbolAddress((void**)&p_bsum, g_bsum);
    cudaGetSymbolAddress((void**)&p_rowptr, g_rowptr);
    cudaGetSymbolAddress((void**)&p_cursor, g_cursor);
    cudaGetSymbolAddress((void**)&p_csr, g_csr);
    cudaGetSymbolAddress((void**)&p_colsum, g_colsum);
    cudaGetSymbolAddress((void**)&p_sumsq, g_sumsq);
    cudaGetSymbolAddress((void**)&p_mu, g_mu);
    cudaGetSymbolAddress((void**)&p_inv, g_inv);

    const int SMEM_TC = (2 * 128 * W_STRIDE + 2 * 128 * X_STRIDE) * 2; // bytes
    static int inited = 0;
    static cudaStream_t s2;
    static cudaEvent_t evFork, evJoin;
    if (!inited) {
        cudaFuncSetAttribute(k_gemm_tc<float>, cudaFuncAttributeMaxDynamicSharedMemorySize,
                             SMEM_TC);
        cudaFuncSetAttribute(k_gemm_tc<__half>, cudaFuncAttributeMaxDynamicSharedMemorySize,
                             SMEM_TC);
        cudaStreamCreateWithFlags(&s2, cudaStreamNonBlocking);
        cudaEventCreateWithFlags(&evFork, cudaEventDisableTiming);
        cudaEventCreateWithFlags(&evJoin, cudaEventDisableTiming);
        inited = 1;
    }

    const int BT = 256;
    const int nBlkN = (N + BT - 1) / BT;
    const int nBlkE = (E + BT - 1) / BT;
    const int nBlkGemm = (N + 127) / 128;
    const int nScan = (N + 1023) / 1024;
    const int nBlkAgg = 1480;

    // --- degree count (needed by both branches) ---
    cudaMemsetAsync(p_degi, 0, (size_t)N * sizeof(int));
    k_deg_count<<<nBlkE, BT>>>(dst, p_degi, E);
    // fork point: scans depend only on deg_count
    cudaEventRecord(evFork, 0);
    cudaStreamWaitEvent(s2, evFork, 0);

    // main stream continues; launch calls ordered so gemm1 is the 5th kernel
    k_zero_stats<<<1, DD>>>(p_colsum, p_sumsq);
    k_dinv<<<nBlkN, BT>>>(p_degi, p_dinv, N);
    k_gemm_tc<float><<<nBlkGemm, BT, SMEM_TC>>>(x, W1, p_h, p_mu, p_inv, p_dinv, 0, N);

    // CSR build on s2 (graph edges: depends on evFork only — overlaps gemm1)
    k_scan1<<<nScan, 1024, 0, s2>>>(p_degi, p_incl, p_bsum, N);
    k_scan2<<<1, 128, 0, s2>>>(p_bsum, nScan);
    k_scan3<<<nBlkN, BT, 0, s2>>>(p_degi, p_incl, p_bsum, p_rowptr, p_cursor, N);
    k_scatter<<<nBlkE, BT, 0, s2>>>(src, dst, p_cursor, p_csr, E);
    cudaEventRecord(evJoin, s2);

    // --- join: aggregation needs CSR ---
    cudaStreamWaitEvent(0, evJoin, 0);

    // ---- Layer 1 (agg computes mu/inv via fused finalize) ----
    k_aggregate<__half, false, true><<<nBlkAgg, BT>>>(
        p_h, p_rowptr, p_csr, p_dinv, p_agg, nullptr, p_colsum, p_sumsq, p_mu, p_inv, N);

    // ---- Layer 2 (PairNorm+ReLU fused into GEMM X-load) ----
    k_gemm_tc<__half><<<nBlkGemm, BT, SMEM_TC>>>(p_agg, W2, p_h, p_mu, p_inv, p_dinv, 1, N);
    k_aggregate<__half, false, true><<<nBlkAgg, BT>>>(
        p_h, p_rowptr, p_csr, p_dinv, p_agg, nullptr, p_colsum, p_sumsq, p_mu, p_inv, N);

    // ---- Layer 3 (output = agg + b3, directly into d_out, fp32) ----
    k_gemm_tc<__half><<<nBlkGemm, BT, SMEM_TC>>>(p_agg, W3, p_h, p_mu, p_inv, p_dinv, 1, N);
    k_aggregate<float, true, false><<<nBlkAgg, BT>>>(
        p_h, p_rowptr, p_csr, p_dinv, out, b3, nullptr, nullptr, nullptr, nullptr, N);
}

// round 14
// speedup vs baseline: 1.0254x; 1.0254x over previous
#include <cuda_runtime.h>
#include <cuda_bf16.h>
#include <cuda_fp16.h>
#include <math.h>
#include <cstdint>

#define DD 128
#define MAXN 100000
#define MAXE 3200000
#define MAXND (MAXN * DD)

// Scratch (static device globals; allocation is forbidden)
__device__ __half g_h[MAXND];      // GEMM output in fp16 (pre-scaled by dinv[row])
__device__ __half g_agg[MAXND];    // aggregation output fp16 (input to next layer)
__device__ int   g_degi[MAXN];
__device__ float g_dinv[MAXN];
__device__ int   g_incl[MAXN];
__device__ int   g_bsum[128];
__device__ int   g_rowptr[MAXN + 1];
__device__ int   g_cursor[MAXN];
__device__ int   g_csr[MAXE];
__device__ float g_colsum[DD];
__device__ float g_sumsq[1];
__device__ float g_mu[DD];
__device__ float g_inv[1];
__device__ unsigned g_done;        // last-block-done counter (zero-initialized)

// ---------------------------------------------------------------------------
__global__ void k_deg_count(const int* __restrict__ dst, int* deg, int E) {
    int e = blockIdx.x * blockDim.x + threadIdx.x;
    if (e < E) atomicAdd(&deg[dst[e]], 1);
}

__global__ void k_dinv(const int* __restrict__ deg, float* dinv, int N) {
    int i = blockIdx.x * blockDim.x + threadIdx.x;
    if (i < N) dinv[i] = rsqrtf((float)(deg[i] + 1));  // +1 self-loop
}

__global__ void k_scan1(const int* __restrict__ deg, int* incl, int* bsum, int N) {
    __shared__ int sh[1024];
    int i = blockIdx.x * 1024 + threadIdx.x;
    int v = (i < N) ? deg[i] : 0;
    sh[threadIdx.x] = v;
    __syncthreads();
    for (int o = 1; o < 1024; o <<= 1) {
        int t = (threadIdx.x >= o) ? sh[threadIdx.x - o] : 0;
        __syncthreads();
        sh[threadIdx.x] += t;
        __syncthreads();
    }
    if (i < N) incl[i] = sh[threadIdx.x];
    if (threadIdx.x == 1023) bsum[blockIdx.x] = sh[1023];
}

__global__ void k_scan2(int* bsum, int nb) {
    __shared__ int sh[128];
    int t = threadIdx.x;
    int v = (t < nb) ? bsum[t] : 0;
    sh[t] = v;
    __syncthreads();
    for (int o = 1; o < 128; o <<= 1) {
        int u = (t >= o) ? sh[t - o] : 0;
        __syncthreads();
        sh[t] += u;
        __syncthreads();
    }
    if (t < nb) bsum[t] = sh[t] - v;  // exclusive
}

__global__ void k_scan3(const int* __restrict__ deg, const int* __restrict__ incl,
                        const int* __restrict__ bsum, int* rowptr, int* cursor, int N) {
    int i = blockIdx.x * blockDim.x + threadIdx.x;
    if (i < N) {
        int dg = deg[i];
        int ex = incl[i] - dg + bsum[i >> 10];
        rowptr[i] = ex;
        cursor[i] = ex;
        if (i == N - 1) rowptr[N] = ex + dg;
    }
}

__global__ void k_scatter(const int* __restrict__ src, const int* __restrict__ dst,
                          int* cursor, int* csr, int E) {
    int e = blockIdx.x * blockDim.x + threadIdx.x;
    if (e < E) {
        int pos = atomicAdd(&cursor[dst[e]], 1);
        csr[pos] = src[e];
    }
}

// ---------------------------------------------------------------------------
// Tensor-core GEMM: H[N,128] = f(X)[N,128] @ W[128,128] * dinv[row], fp16 out.
// bf16 3-product split, fp32 accumulation. ldmatrix fragment loads.
// Warp tile 32x64 (4x2 warp grid): halves per-warp B smem traffic vs 16x128.
#define W_STRIDE 136
#define X_STRIDE 24

__device__ __forceinline__ uint32_t smem_u32(const void* p) {
    uint32_t a;
    asm("{.reg .u64 t; cvta.to.shared.u64 t, %1; cvt.u32.u64 %0, t;}" : "=r"(a) : "l"(p));
    return a;
}

__device__ __forceinline__ void ldsm_x4(unsigned* r, uint32_t addr) {
    asm volatile("ldmatrix.sync.aligned.m8n8.x4.shared.b16 {%0,%1,%2,%3}, [%4];"
                 : "=r"(r[0]), "=r"(r[1]), "=r"(r[2]), "=r"(r[3]) : "r"(addr));
}
__device__ __forceinline__ void ldsm_x2(unsigned* r, uint32_t addr) {
    asm volatile("ldmatrix.sync.aligned.m8n8.x2.shared.b16 {%0,%1}, [%2];"
                 : "=r"(r[0]), "=r"(r[1]) : "r"(addr));
}

__device__ __forceinline__ void load8(const float* p, float* v) {
    float4 a = *(const float4*)p;
    float4 b = *(const float4*)(p + 4);
    v[0] = a.x; v[1] = a.y; v[2] = a.z; v[3] = a.w;
    v[4] = b.x; v[5] = b.y; v[6] = b.z; v[7] = b.w;
}
__device__ __forceinline__ void load8(const __half* p, float* v) {
    uint4 u = *(const uint4*)p;
    const __half2* h = reinterpret_cast<const __half2*>(&u);
#pragma unroll
    for (int i = 0; i < 4; i++) {
        float2 f = __half22float2(h[i]);
        v[2 * i] = f.x;
        v[2 * i + 1] = f.y;
    }
}

__device__ __forceinline__ void mma16816(float* c, const unsigned* a, const unsigned* b) {
    asm volatile(
        "mma.sync.aligned.m16n8k16.row.col.f32.bf16.bf16.f32 "
        "{%0,%1,%2,%3},{%4,%5,%6,%7},{%8,%9},{%0,%1,%2,%3};"
        : "+f"(c[0]), "+f"(c[1]), "+f"(c[2]), "+f"(c[3])
        : "r"(a[0]), "r"(a[1]), "r"(a[2]), "r"(a[3]), "r"(b[0]), "r"(b[1]));
}

template <typename IT>
__global__ void __launch_bounds__(256, 2)
k_gemm_tc(const IT* __restrict__ X, const float* __restrict__ W,
          __half* __restrict__ H, const float* __restrict__ mu,
          const float* __restrict__ invp, const float* __restrict__ dinv,
          int applyNorm, int N) {
    extern __shared__ __nv_bfloat16 smem[];
    __nv_bfloat16* wh = smem;                       // [128][W_STRIDE]
    __nv_bfloat16* wl = wh + 128 * W_STRIDE;
    __nv_bfloat16* xh = wl + 128 * W_STRIDE;        // [128][X_STRIDE]
    __nv_bfloat16* xl = xh + 128 * X_STRIDE;

    const int tid = threadIdx.x;
    const int warp = tid >> 5;
    const int lane = tid & 31;
    const int g = lane >> 2;
    const int tg = lane & 3;
    const int row0 = blockIdx.x * 128;
    const float inv = applyNorm ? invp[0] : 0.0f;

    // Stage W (hi + lo), transposed to [n][k]
    for (int i = tid; i < DD * DD; i += 256) {
        int k = i >> 7, n = i & 127;
        float w = W[i];
        __nv_bfloat16 hi = __float2bfloat16(w);
        float lo = w - __bfloat162float(hi);
        wh[n * W_STRIDE + k] = hi;
        wl[n * W_STRIDE + k] = __float2bfloat16(lo);
    }

    float c[16][4];
#pragma unroll
    for (int i = 0; i < 16; i++)
#pragma unroll
        for (int j = 0; j < 4; j++) c[i][j] = 0.0f;

    // warp grid: 4 row-groups x 2 col-groups
    const int rg = warp >> 1;           // 0..3
    const int cg = warp & 1;            // 0..1
    const int arow = rg * 32;
    const int sr = tid >> 1;            // staging row 0..127
    const int sc8 = (tid & 1) << 3;     // staging col 0 or 8
    const int gr = row0 + sr;
    const bool valid = (gr < N);
    const IT* xrow = X + ((size_t)gr << 7) + sc8;   // + ch*16 per chunk

    // ldmatrix lane addressing
    const int l8 = ((lane >> 3) & 1) * 8;
    const int l16 = ((lane >> 4) & 1) * 8;
    const uint32_t xh_u32 = smem_u32(xh);
    const uint32_t a_off0 = (uint32_t)((arow + l8 + (lane & 7)) * X_STRIDE + l16) * 2;
    const uint32_t a_off1 = (uint32_t)((arow + 16 + l8 + (lane & 7)) * X_STRIDE + l16) * 2;
    const uint32_t a_lo = (uint32_t)(128 * X_STRIDE) * 2;
    const uint32_t wh_u32 = smem_u32(wh);
    const uint32_t b_lane_off =
        (uint32_t)(((lane & 7) + cg * 64) * W_STRIDE + l8) * 2;
    const uint32_t b_lo = (uint32_t)(128 * W_STRIDE) * 2;

    float v[8];
    if (valid) load8(xrow, v);
    else {
#pragma unroll
        for (int q = 0; q < 8; q++) v[q] = 0.0f;
    }

    for (int ch = 0; ch < 8; ch++) {
        float sv[8];
        if (valid && applyNorm) {
#pragma unroll
            for (int q = 0; q < 8; q++)
                sv[q] = fmaxf((v[q] - __ldg(&mu[ch * 16 + sc8 + q])) * inv, 0.0f);
        } else {
#pragma unroll
            for (int q = 0; q < 8; q++) sv[q] = v[q];
        }
        __syncthreads();
        {
            __nv_bfloat16 hi8[8], lo8[8];
#pragma unroll
            for (int q = 0; q < 8; q++) {
                hi8[q] = __float2bfloat16(sv[q]);
                lo8[q] = __float2bfloat16(sv[q] - __bfloat162float(hi8[q]));
            }
            *(uint4*)(xh + sr * X_STRIDE + sc8) = *(uint4*)hi8;
            *(uint4*)(xl + sr * X_STRIDE + sc8) = *(uint4*)lo8;
        }
        __syncthreads();

        if (ch < 7) {
            if (valid) load8(xrow + (ch + 1) * 16, v);
        }

        unsigned ah[8], al[8];
        ldsm_x4(ah, xh_u32 + a_off0);
        ldsm_x4(ah + 4, xh_u32 + a_off1);
        ldsm_x4(al, xh_u32 + a_off0 + a_lo);
        ldsm_x4(al + 4, xh_u32 + a_off1 + a_lo);

        const int kc = ch * 16;
        const uint32_t bbase = wh_u32 + b_lane_off + (uint32_t)kc * 2;
#pragma unroll
        for (int nt = 0; nt < 8; nt++) {
            unsigned bh[2], bl[2];
            const uint32_t baddr = bbase + (uint32_t)(nt * 8 * W_STRIDE) * 2;
            ldsm_x2(bh, baddr);
            ldsm_x2(bl, baddr + b_lo);
            mma16816(c[nt], ah, bh);
            mma16816(c[nt], ah, bl);
            mma16816(c[nt], al, bh);
            mma16816(c[8 + nt], ah + 4, bh);
            mma16816(c[8 + nt], ah + 4, bl);
            mma16816(c[8 + nt], al + 4, bh);
        }
    }

    // Epilogue: scale by dinv[row], store half2
#pragma unroll
    for (int mt = 0; mt < 2; mt++) {
        const int r0 = row0 + arow + mt * 16 + g;
        const int r1 = r0 + 8;
        const float dv0 = (r0 < N) ? dinv[r0] : 0.0f;
        const float dv1 = (r1 < N) ? dinv[r1] : 0.0f;
#pragma unroll
        for (int nt = 0; nt < 8; nt++) {
            const float* cc = c[mt * 8 + nt];
            int col = cg * 64 + nt * 8 + 2 * tg;
            if (r0 < N)
                *(__half2*)(H + ((size_t)r0 << 7) + col) =
                    __floats2half2_rn(cc[0] * dv0, cc[1] * dv0);
            if (r1 < N)
                *(__half2*)(H + ((size_t)r1 << 7) + col) =
                    __floats2half2_rn(cc[2] * dv1, cc[3] * dv1);
        }
    }
}

// ---------------------------------------------------------------------------
// CSR gather aggregation (R12-proven): 2 rows per warp-load, 8 neighbors/iter.
// STATS path fuses the PairNorm finalize via last-block-done pattern.
__device__ __forceinline__ void add8(float* a, uint4 u) {
    __half2* p = reinterpret_cast<__half2*>(&u);
#pragma unroll
    for (int i = 0; i < 4; i++) {
        float2 f = __half22float2(p[i]);
        a[2 * i] += f.x;
        a[2 * i + 1] += f.y;
    }
}

template <typename OT, bool HASBIAS, bool STATS>
__global__ void k_aggregate(const __half* __restrict__ h, const int* __restrict__ rowptr,
                            const int* __restrict__ csr, const float* __restrict__ dinv,
                            OT* __restrict__ out, const float* __restrict__ bias,
                            float* colsum, float* sumsq, float* mu, float* invp, int N) {
    __shared__ float s_col[DD];
    __shared__ float s_ss;
    if (STATS) {
        if (threadIdx.x < DD) s_col[threadIdx.x] = 0.0f;
        if (threadIdx.x == 0) s_ss = 0.0f;
        __syncthreads();
    }
    const int lane = threadIdx.x & 31;
    const int half = lane >> 4;
    const int cpos = lane & 15;
    const int warp = (blockIdx.x * blockDim.x + threadIdx.x) >> 5;
    const int nwarps = (gridDim.x * blockDim.x) >> 5;
    const uint4* hp = reinterpret_cast<const uint4*>(h);  // row stride 16 uint4

    float cs[8];
    float ssacc = 0.0f;
    if (STATS) {
#pragma unroll
        for (int i = 0; i < 8; i++) cs[i] = 0.0f;
    }

    for (int d = warp; d < N; d += nwarps) {
        float a[8];
#pragma unroll
        for (int i = 0; i < 8; i++) a[i] = 0.0f;

        if (half == 0) add8(a, __ldg(&hp[((size_t)d << 4) + cpos]));  // self

        int j = __ldg(&rowptr[d]);
        const int je = __ldg(&rowptr[d + 1]);
        for (; j + 8 <= je; j += 8) {
            int s0 = __ldg(&csr[j + 0 + half]);
            int s1 = __ldg(&csr[j + 2 + half]);
            int s2 = __ldg(&csr[j + 4 + half]);
            int s3 = __ldg(&csr[j + 6 + half]);
            uint4 u0 = __ldg(&hp[((size_t)s0 << 4) + cpos]);
            uint4 u1 = __ldg(&hp[((size_t)s1 << 4) + cpos]);
            uint4 u2 = __ldg(&hp[((size_t)s2 << 4) + cpos]);
            uint4 u3 = __ldg(&hp[((size_t)s3 << 4) + cpos]);
            add8(a, u0); add8(a, u1); add8(a, u2); add8(a, u3);
        }
        for (; j + 2 <= je; j += 2) {
            int s = __ldg(&csr[j + half]);
            add8(a, __ldg(&hp[((size_t)s << 4) + cpos]));
        }
        if (j < je && half == 0) {
            int s = __ldg(&csr[j]);
            add8(a, __ldg(&hp[((size_t)s << 4) + cpos]));
        }

#pragma unroll
        for (int i = 0; i < 8; i++)
            a[i] += __shfl_xor_sync(0xffffffffu, a[i], 16);

        const float sc = __ldg(&dinv[d]);
        float o[8];
#pragma unroll
        for (int i = 0; i < 8; i++) o[i] = a[i] * sc;

        if (HASBIAS) {
            const float4 b = reinterpret_cast<const float4*>(bias)[cpos * 2 + half];
            float4 v = make_float4(o[half * 4 + 0] + b.x, o[half * 4 + 1] + b.y,
                                   o[half * 4 + 2] + b.z, o[half * 4 + 3] + b.w);
            *reinterpret_cast<float4*>(
                reinterpret_cast<float*>(out) + ((size_t)d << 7) + cpos * 8 + half * 4) = v;
        } else {
            __half2 v0 = __floats2half2_rn(o[half * 4 + 0], o[half * 4 + 1]);
            __half2 v1 = __floats2half2_rn(o[half * 4 + 2], o[half * 4 + 3]);
            uint2 pk;
            pk.x = *reinterpret_cast<unsigned*>(&v0);
            pk.y = *reinterpret_cast<unsigned*>(&v1);
            *reinterpret_cast<uint2*>(
                reinterpret_cast<__half*>(out) + ((size_t)d << 7) + cpos * 8 + half * 4) = pk;
        }

        if (STATS && half == 0) {
#pragma unroll
            for (int i = 0; i < 8; i++) {
                cs[i] += o[i];
                ssacc += o[i] * o[i];
            }
        }
    }

    if (STATS) {
        if (half == 0) {
#pragma unroll
            for (int i = 0; i < 8; i++) atomicAdd(&s_col[cpos * 8 + i], cs[i]);
        }
        for (int o = 16; o > 0; o >>= 1) ssacc += __shfl_down_sync(0xffffffff, ssacc, o);
        if (lane == 0) atomicAdd(&s_ss, ssacc);
        __syncthreads();
        if (threadIdx.x < DD) atomicAdd(&colsum[threadIdx.x], s_col[threadIdx.x]);
        if (threadIdx.x == 0) atomicAdd(sumsq, s_ss);

        // --- fused finalize: last block computes mu/inv and resets stats ---
        __threadfence();
        __shared__ unsigned rank_sh;
        if (threadIdx.x == 0) rank_sh = atomicAdd(&g_done, 1u);
        __syncthreads();
        if (rank_sh == gridDim.x - 1) {
            __threadfence();
            const int c = threadIdx.x;
            if (c < DD) {
                float m = colsum[c] / (float)N;
                mu[c] = m;
                colsum[c] = 0.0f;
                s_col[c] = m * m;
            }
            __syncthreads();
            for (int o = 64; o > 0; o >>= 1) {
                if (c < o) s_col[c] += s_col[c + o];
                __syncthreads();
            }
            if (c == 0) {
                float var = fmaxf(sumsq[0] / (float)N - s_col[0], 0.0f);
                invp[0] = 1.0f / (sqrtf(var) + 1e-8f);
                sumsq[0] = 0.0f;
                g_done = 0;
            }
        }
    }
}

// ---------------------------------------------------------------------------
__global__ void k_zero_stats(float* colsum, float* sumsq) {
    int i = threadIdx.x;
    if (i < DD) colsum[i] = 0.0f;
    if (i == 0) { sumsq[0] = 0.0f; g_done = 0; }
}

// ---------------------------------------------------------------------------
extern "C" void kernel_launch(void* const* d_in, const int* in_sizes, int n_in,
                              void* d_out, int out_size) {
    const float* x  = (const float*)d_in[0];
    const int* ei   = (const int*)d_in[1];
    const float* W1 = (const float*)d_in[2];
    const float* W2 = (const float*)d_in[4];
    const float* W3 = (const float*)d_in[6];
    const float* b3 = (const float*)d_in[7];
    float* out = (float*)d_out;

    const int N = in_sizes[0] / DD;
    const int E = in_sizes[1] / 2;
    const int* src = ei;
    const int* dst = ei + E;

    float *p_dinv, *p_colsum, *p_sumsq, *p_mu, *p_inv;
    __half *p_h, *p_agg;
    int *p_degi, *p_incl, *p_bsum, *p_rowptr, *p_cursor, *p_csr;
    cudaGetSymbolAddress((void**)&p_h, g_h);
    cudaGetSymbolAddress((void**)&p_agg, g_agg);
    cudaGetSymbolAddress((void**)&p_degi, g_degi);
    cudaGetSymbolAddress((void**)&p_dinv, g_dinv);
    cudaGetSymbolAddress((void**)&p_incl, g_incl);
    cudaGetSymbolAddress((void**)&p_bsum, g_bsum);
    cudaGetSymbolAddress((void**)&p_rowptr, g_rowptr);
    cudaGetSymbolAddress((void**)&p_cursor, g_cursor);
    cudaGetSymbolAddress((void**)&p_csr, g_csr);
    cudaGetSymbolAddress((void**)&p_colsum, g_colsum);
    cudaGetSymbolAddress((void**)&p_sumsq, g_sumsq);
    cudaGetSymbolAddress((void**)&p_mu, g_mu);
    cudaGetSymbolAddress((void**)&p_inv, g_inv);

    const int SMEM_TC = (2 * 128 * W_STRIDE + 2 * 128 * X_STRIDE) * 2; // bytes
    static int inited = 0;
    static cudaStream_t s2;
    static cudaEvent_t evFork, evJoin;
    if (!inited) {
        cudaFuncSetAttribute(k_gemm_tc<float>, cudaFuncAttributeMaxDynamicSharedMemorySize,
                             SMEM_TC);
        cudaFuncSetAttribute(k_gemm_tc<__half>, cudaFuncAttributeMaxDynamicSharedMemorySize,
                             SMEM_TC);
        cudaStreamCreateWithFlags(&s2, cudaStreamNonBlocking);
        cudaEventCreateWithFlags(&evFork, cudaEventDisableTiming);
        cudaEventCreateWithFlags(&evJoin, cudaEventDisableTiming);
        inited = 1;
    }

    const int BT = 256;
    const int nBlkN = (N + BT - 1) / BT;
    const int nBlkE = (E + BT - 1) / BT;
    const int nBlkGemm = (N + 127) / 128;
    const int nScan = (N + 1023) / 1024;
    const int nBlkAgg = 1480;

    // --- degree count (needed by both branches) ---
    cudaMemsetAsync(p_degi, 0, (size_t)N * sizeof(int));
    k_deg_count<<<nBlkE, BT>>>(dst, p_degi, E);
    // fork point: scans depend only on deg_count
    cudaEventRecord(evFork, 0);
    cudaStreamWaitEvent(s2, evFork, 0);

    // main stream continues; launch calls ordered so gemm1 is the 5th kernel
    k_zero_stats<<<1, DD>>>(p_colsum, p_sumsq);
    k_dinv<<<nBlkN, BT>>>(p_degi, p_dinv, N);
    k_gemm_tc<float><<<nBlkGemm, BT, SMEM_TC>>>(x, W1, p_h, p_mu, p_inv, p_dinv, 0, N);

    // CSR build on s2 (graph edges: depends on evFork only — overlaps gemm1)
    k_scan1<<<nScan, 1024, 0, s2>>>(p_degi, p_incl, p_bsum, N);
    k_scan2<<<1, 128, 0, s2>>>(p_bsum, nScan);
    k_scan3<<<nBlkN, BT, 0, s2>>>(p_degi, p_incl, p_bsum, p_rowptr, p_cursor, N);
    k_scatter<<<nBlkE, BT, 0, s2>>>(src, dst, p_cursor, p_csr, E);
    cudaEventRecord(evJoin, s2);

    // --- join: aggregation needs CSR ---
    cudaStreamWaitEvent(0, evJoin, 0);

    // ---- Layer 1 (agg computes mu/inv via fused finalize) ----
    k_aggregate<__half, false, true><<<nBlkAgg, BT>>>(
        p_h, p_rowptr, p_csr, p_dinv, p_agg, nullptr, p_colsum, p_sumsq, p_mu, p_inv, N);

    // ---- Layer 2 (PairNorm+ReLU fused into GEMM X-load) ----
    k_gemm_tc<__half><<<nBlkGemm, BT, SMEM_TC>>>(p_agg, W2, p_h, p_mu, p_inv, p_dinv, 1, N);
    k_aggregate<__half, false, true><<<nBlkAgg, BT>>>(
        p_h, p_rowptr, p_csr, p_dinv, p_agg, nullptr, p_colsum, p_sumsq, p_mu, p_inv, N);

    // ---- Layer 3 (output = agg + b3, directly into d_out, fp32) ----
    k_gemm_tc<__half><<<nBlkGemm, BT, SMEM_TC>>>(p_agg, W3, p_h, p_mu, p_inv, p_dinv, 1, N);
    k_aggregate<float, true, false><<<nBlkAgg, BT>>>(
        p_h, p_rowptr, p_csr, p_dinv, out, b3, nullptr, nullptr, nullptr, nullptr, N);
}

// round 17
// speedup vs baseline: 1.0348x; 1.0092x over previous
#include <cuda_runtime.h>
#include <cuda_bf16.h>
#include <cuda_fp16.h>
#include <math.h>
#include <cstdint>

#define DD 128
#define MAXN 100000
#define MAXE 3200000
#define MAXND (MAXN * DD)

// Scratch (static device globals; allocation is forbidden)
__device__ __half g_h[MAXND];      // GEMM output in fp16 (pre-scaled by dinv[row])
__device__ __half g_agg[MAXND];    // aggregation output fp16 (input to next layer)
__device__ int   g_degi[MAXN];
__device__ float g_dinv[MAXN];
__device__ int   g_incl[MAXN];
__device__ int   g_bsum[128];
__device__ int   g_rowptr[MAXN + 1];
__device__ int   g_cursor[MAXN];
__device__ int   g_csr[MAXE];
__device__ float g_colsum[DD];
__device__ float g_sumsq[1];
__device__ float g_mu[DD];
__device__ float g_inv[1];
__device__ unsigned g_done;        // last-block-done counter (zero-initialized)

// ---------------------------------------------------------------------------
__global__ void k_deg_count(const int* __restrict__ dst, int* deg, int E) {
    int e = blockIdx.x * blockDim.x + threadIdx.x;
    if (e < E) atomicAdd(&deg[dst[e]], 1);
}

__global__ void k_dinv(const int* __restrict__ deg, float* dinv, int N) {
    int i = blockIdx.x * blockDim.x + threadIdx.x;
    if (i < N) dinv[i] = rsqrtf((float)(deg[i] + 1));  // +1 self-loop
}

__global__ void k_scan1(const int* __restrict__ deg, int* incl, int* bsum, int N) {
    __shared__ int sh[1024];
    int i = blockIdx.x * 1024 + threadIdx.x;
    int v = (i < N) ? deg[i] : 0;
    sh[threadIdx.x] = v;
    __syncthreads();
    for (int o = 1; o < 1024; o <<= 1) {
        int t = (threadIdx.x >= o) ? sh[threadIdx.x - o] : 0;
        __syncthreads();
        sh[threadIdx.x] += t;
        __syncthreads();
    }
    if (i < N) incl[i] = sh[threadIdx.x];
    if (threadIdx.x == 1023) bsum[blockIdx.x] = sh[1023];
}

__global__ void k_scan2(int* bsum, int nb) {
    __shared__ int sh[128];
    int t = threadIdx.x;
    int v = (t < nb) ? bsum[t] : 0;
    sh[t] = v;
    __syncthreads();
    for (int o = 1; o < 128; o <<= 1) {
        int u = (t >= o) ? sh[t - o] : 0;
        __syncthreads();
        sh[t] += u;
        __syncthreads();
    }
    if (t < nb) bsum[t] = sh[t] - v;  // exclusive
}

__global__ void k_scan3(const int* __restrict__ deg, const int* __restrict__ incl,
                        const int* __restrict__ bsum, int* rowptr, int* cursor, int N) {
    int i = blockIdx.x * blockDim.x + threadIdx.x;
    if (i < N) {
        int dg = deg[i];
        int ex = incl[i] - dg + bsum[i >> 10];
        rowptr[i] = ex;
        cursor[i] = ex;
        if (i == N - 1) rowptr[N] = ex + dg;
    }
}

__global__ void k_scatter(const int* __restrict__ src, const int* __restrict__ dst,
                          int* cursor, int* csr, int E) {
    int e = blockIdx.x * blockDim.x + threadIdx.x;
    if (e < E) {
        int pos = atomicAdd(&cursor[dst[e]], 1);
        csr[pos] = src[e];
    }
}

// ---------------------------------------------------------------------------
// Tensor-core GEMM: H[N,128] = f(X)[N,128] @ W[128,128] * dinv[row], fp16 out.
// bf16 3-product split, fp32 accumulation. Warp tile 32x64 (4x2 warp grid).
// A-fragments built DIRECTLY from global X in mma ownership pattern —
// no X smem staging, no __syncthreads in the k-loop. W staged once.
#define W_STRIDE 136

__device__ __forceinline__ uint32_t smem_u32(const void* p) {
    uint32_t a;
    asm("{.reg .u64 t; cvta.to.shared.u64 t, %1; cvt.u32.u64 %0, t;}" : "=r"(a) : "l"(p));
    return a;
}

__device__ __forceinline__ void ldsm_x2(unsigned* r, uint32_t addr) {
    asm volatile("ldmatrix.sync.aligned.m8n8.x2.shared.b16 {%0,%1}, [%2];"
                 : "=r"(r[0]), "=r"(r[1]) : "r"(addr));
}

__device__ __forceinline__ float2 load2(const float* p) {
    return *(const float2*)p;
}
__device__ __forceinline__ float2 load2(const __half* p) {
    return __half22float2(*(const __half2*)p);
}

__device__ __forceinline__ void mma16816(float* c, const unsigned* a, const unsigned* b) {
    asm volatile(
        "mma.sync.aligned.m16n8k16.row.col.f32.bf16.bf16.f32 "
        "{%0,%1,%2,%3},{%4,%5,%6,%7},{%8,%9},{%0,%1,%2,%3};"
        : "+f"(c[0]), "+f"(c[1]), "+f"(c[2]), "+f"(c[3])
        : "r"(a[0]), "r"(a[1]), "r"(a[2]), "r"(a[3]), "r"(b[0]), "r"(b[1]));
}

template <typename IT>
__global__ void __launch_bounds__(256, 2)
k_gemm_tc(const IT* __restrict__ X, const float* __restrict__ W,
          __half* __restrict__ H, const float* __restrict__ mu,
          const float* __restrict__ invp, const float* __restrict__ dinv,
          int applyNorm, int N) {
    extern __shared__ __nv_bfloat16 smem[];
    __nv_bfloat16* wh = smem;                       // [128][W_STRIDE]
    __nv_bfloat16* wl = wh + 128 * W_STRIDE;

    const int tid = threadIdx.x;
    const int warp = tid >> 5;
    const int lane = tid & 31;
    const int g = lane >> 2;
    const int tg = lane & 3;
    const int row0 = blockIdx.x * 128;
    const float inv = applyNorm ? invp[0] : 0.0f;

    // Stage W (hi + lo), transposed to [n][k]; the ONLY block sync follows.
    for (int i = tid; i < DD * DD; i += 256) {
        int k = i >> 7, n = i & 127;
        float w = W[i];
        __nv_bfloat16 hi = __float2bfloat16(w);
        float lo = w - __bfloat162float(hi);
        wh[n * W_STRIDE + k] = hi;
        wl[n * W_STRIDE + k] = __float2bfloat16(lo);
    }
    __syncthreads();

    float c[16][4];
#pragma unroll
    for (int i = 0; i < 16; i++)
#pragma unroll
        for (int j = 0; j < 4; j++) c[i][j] = 0.0f;

    // warp grid: 4 row-groups x 2 col-groups
    const int rg = warp >> 1;           // 0..3
    const int cg = warp & 1;            // 0..1
    const int arow = rg * 32;

    // this lane's 4 A-rows (mma ownership) and k-column offsets
    const int rA = row0 + arow + g;
    const int rB = rA + 8;
    const int rC = rA + 16;
    const int rD = rA + 24;
    const bool vA = rA < N, vB = rB < N, vC = rC < N, vD = rD < N;
    const IT* xA = X + ((size_t)rA << 7);
    const IT* xB = X + ((size_t)rB << 7);
    const IT* xC = X + ((size_t)rC << 7);
    const IT* xD = X + ((size_t)rD << 7);
    const int colL = 2 * tg;            // cols kc+colL, +1
    const int colH = 8 + 2 * tg;        // cols kc+colH, +1

    // B ldsm addressing (proven layout from R12-R14)
    const int l8 = ((lane >> 3) & 1) * 8;
    const uint32_t wh_u32 = smem_u32(wh);
    const uint32_t b_lane_off =
        (uint32_t)(((lane & 7) + cg * 64) * W_STRIDE + l8) * 2;
    const uint32_t b_lo = (uint32_t)(128 * W_STRIDE) * 2;

    const float2 z2 = make_float2(0.0f, 0.0f);
    float2 v[8];
    // prefetch chunk 0: v[i] rows {A,B,A,B,C,D,C,D}, cols {L,L,H,H,L,L,H,H}
    v[0] = vA ? load2(xA + colL) : z2;
    v[1] = vB ? load2(xB + colL) : z2;
    v[2] = vA ? load2(xA + colH) : z2;
    v[3] = vB ? load2(xB + colH) : z2;
    v[4] = vC ? load2(xC + colL) : z2;
    v[5] = vD ? load2(xD + colL) : z2;
    v[6] = vC ? load2(xC + colH) : z2;
    v[7] = vD ? load2(xD + colH) : z2;

    for (int ch = 0; ch < 8; ch++) {
        const int kc = ch * 16;
        float2 mlo, mhi;
        if (applyNorm) {
            mlo = *(const float2*)(mu + kc + colL);
            mhi = *(const float2*)(mu + kc + colH);
        }
        // build A fragments (hi & lo) in registers
        unsigned ah[8], al[8];
#pragma unroll
        for (int i = 0; i < 8; i++) {
            float f0 = v[i].x, f1 = v[i].y;
            if (applyNorm) {
                // i in {2,3,6,7} use high-col mu (invalid rows produce junk;
                // their accumulators are never stored)
                float2 m = ((i & 2) != 0) ? mhi : mlo;
                f0 = fmaxf((f0 - m.x) * inv, 0.0f);
                f1 = fmaxf((f1 - m.y) * inv, 0.0f);
            }
            __nv_bfloat16 h0 = __float2bfloat16(f0);
            __nv_bfloat16 h1 = __float2bfloat16(f1);
            __nv_bfloat162 hp; hp.x = h0; hp.y = h1;
            ah[i] = *reinterpret_cast<unsigned*>(&hp);
            __nv_bfloat16 l0 = __float2bfloat16(f0 - __bfloat162float(h0));
            __nv_bfloat16 l1 = __float2bfloat16(f1 - __bfloat162float(h1));
            __nv_bfloat162 lp; lp.x = l0; lp.y = l1;
            al[i] = *reinterpret_cast<unsigned*>(&lp);
        }
        // prefetch next chunk (latency hidden by MMAs below)
        if (ch < 7) {
            const int kn = kc + 16;
            v[0] = vA ? load2(xA + kn + colL) : z2;
            v[1] = vB ? load2(xB + kn + colL) : z2;
            v[2] = vA ? load2(xA + kn + colH) : z2;
            v[3] = vB ? load2(xB + kn + colH) : z2;
            v[4] = vC ? load2(xC + kn + colL) : z2;
            v[5] = vD ? load2(xD + kn + colL) : z2;
            v[6] = vC ? load2(xC + kn + colH) : z2;
            v[7] = vD ? load2(xD + kn + colH) : z2;
        }

        const uint32_t bbase = wh_u32 + b_lane_off + (uint32_t)kc * 2;
#pragma unroll
        for (int nt = 0; nt < 8; nt++) {
            unsigned bh[2], bl[2];
            const uint32_t baddr = bbase + (uint32_t)(nt * 8 * W_STRIDE) * 2;
            ldsm_x2(bh, baddr);
            ldsm_x2(bl, baddr + b_lo);
            mma16816(c[nt], ah, bh);
            mma16816(c[nt], ah, bl);
            mma16816(c[nt], al, bh);
            mma16816(c[8 + nt], ah + 4, bh);
            mma16816(c[8 + nt], ah + 4, bl);
            mma16816(c[8 + nt], al + 4, bh);
        }
    }

    // Epilogue: scale by dinv[row], store half2
#pragma unroll
    for (int mt = 0; mt < 2; mt++) {
        const int r0 = row0 + arow + mt * 16 + g;
        const int r1 = r0 + 8;
        const float dv0 = (r0 < N) ? dinv[r0] : 0.0f;
        const float dv1 = (r1 < N) ? dinv[r1] : 0.0f;
#pragma unroll
        for (int nt = 0; nt < 8; nt++) {
            const float* cc = c[mt * 8 + nt];
            int col = cg * 64 + nt * 8 + 2 * tg;
            if (r0 < N)
                *(__half2*)(H + ((size_t)r0 << 7) + col) =
                    __floats2half2_rn(cc[0] * dv0, cc[1] * dv0);
            if (r1 < N)
                *(__half2*)(H + ((size_t)r1 << 7) + col) =
                    __floats2half2_rn(cc[2] * dv1, cc[3] * dv1);
        }
    }
}

// ---------------------------------------------------------------------------
// CSR gather aggregation (R12-proven): 2 rows per warp-load, 8 neighbors/iter.
// STATS path fuses the PairNorm finalize via last-block-done pattern.
__device__ __forceinline__ void add8(float* a, uint4 u) {
    __half2* p = reinterpret_cast<__half2*>(&u);
#pragma unroll
    for (int i = 0; i < 4; i++) {
        float2 f = __half22float2(p[i]);
        a[2 * i] += f.x;
        a[2 * i + 1] += f.y;
    }
}

template <typename OT, bool HASBIAS, bool STATS>
__global__ void k_aggregate(const __half* __restrict__ h, const int* __restrict__ rowptr,
                            const int* __restrict__ csr, const float* __restrict__ dinv,
                            OT* __restrict__ out, const float* __restrict__ bias,
                            float* colsum, float* sumsq, float* mu, float* invp, int N) {
    __shared__ float s_col[DD];
    __shared__ float s_ss;
    if (STATS) {
        if (threadIdx.x < DD) s_col[threadIdx.x] = 0.0f;
        if (threadIdx.x == 0) s_ss = 0.0f;
        __syncthreads();
    }
    const int lane = threadIdx.x & 31;
    const int half = lane >> 4;
    const int cpos = lane & 15;
    const int warp = (blockIdx.x * blockDim.x + threadIdx.x) >> 5;
    const int nwarps = (gridDim.x * blockDim.x) >> 5;
    const uint4* hp = reinterpret_cast<const uint4*>(h);  // row stride 16 uint4

    float cs[8];
    float ssacc = 0.0f;
    if (STATS) {
#pragma unroll
        for (int i = 0; i < 8; i++) cs[i] = 0.0f;
    }

    for (int d = warp; d < N; d += nwarps) {
        float a[8];
#pragma unroll
        for (int i = 0; i < 8; i++) a[i] = 0.0f;

        if (half == 0) add8(a, __ldg(&hp[((size_t)d << 4) + cpos]));  // self

        int j = __ldg(&rowptr[d]);
        const int je = __ldg(&rowptr[d + 1]);
        for (; j + 8 <= je; j += 8) {
            int s0 = __ldg(&csr[j + 0 + half]);
            int s1 = __ldg(&csr[j + 2 + half]);
            int s2 = __ldg(&csr[j + 4 + half]);
            int s3 = __ldg(&csr[j + 6 + half]);
            uint4 u0 = __ldg(&hp[((size_t)s0 << 4) + cpos]);
            uint4 u1 = __ldg(&hp[((size_t)s1 << 4) + cpos]);
            uint4 u2 = __ldg(&hp[((size_t)s2 << 4) + cpos]);
            uint4 u3 = __ldg(&hp[((size_t)s3 << 4) + cpos]);
            add8(a, u0); add8(a, u1); add8(a, u2); add8(a, u3);
        }
        for (; j + 2 <= je; j += 2) {
            int s = __ldg(&csr[j + half]);
            add8(a, __ldg(&hp[((size_t)s << 4) + cpos]));
        }
        if (j < je && half == 0) {
            int s = __ldg(&csr[j]);
            add8(a, __ldg(&hp[((size_t)s << 4) + cpos]));
        }

#pragma unroll
        for (int i = 0; i < 8; i++)
            a[i] += __shfl_xor_sync(0xffffffffu, a[i], 16);

        const float sc = __ldg(&dinv[d]);
        float o[8];
#pragma unroll
        for (int i = 0; i < 8; i++) o[i] = a[i] * sc;

        if (HASBIAS) {
            const float4 b = reinterpret_cast<const float4*>(bias)[cpos * 2 + half];
            float4 v = make_float4(o[half * 4 + 0] + b.x, o[half * 4 + 1] + b.y,
                                   o[half * 4 + 2] + b.z, o[half * 4 + 3] + b.w);
            *reinterpret_cast<float4*>(
                reinterpret_cast<float*>(out) + ((size_t)d << 7) + cpos * 8 + half * 4) = v;
        } else {
            __half2 v0 = __floats2half2_rn(o[half * 4 + 0], o[half * 4 + 1]);
            __half2 v1 = __floats2half2_rn(o[half * 4 + 2], o[half * 4 + 3]);
            uint2 pk;
            pk.x = *reinterpret_cast<unsigned*>(&v0);
            pk.y = *reinterpret_cast<unsigned*>(&v1);
            *reinterpret_cast<uint2*>(
                reinterpret_cast<__half*>(out) + ((size_t)d << 7) + cpos * 8 + half * 4) = pk;
        }

        if (STATS && half == 0) {
#pragma unroll
            for (int i = 0; i < 8; i++) {
                cs[i] += o[i];
                ssacc += o[i] * o[i];
            }
        }
    }

    if (STATS) {
        if (half == 0) {
#pragma unroll
            for (int i = 0; i < 8; i++) atomicAdd(&s_col[cpos * 8 + i], cs[i]);
        }
        for (int o = 16; o > 0; o >>= 1) ssacc += __shfl_down_sync(0xffffffff, ssacc, o);
        if (lane == 0) atomicAdd(&s_ss, ssacc);
        __syncthreads();
        if (threadIdx.x < DD) atomicAdd(&colsum[threadIdx.x], s_col[threadIdx.x]);
        if (threadIdx.x == 0) atomicAdd(sumsq, s_ss);

        // --- fused finalize: last block computes mu/inv and resets stats ---
        __threadfence();
        __shared__ unsigned rank_sh;
        if (threadIdx.x == 0) rank_sh = atomicAdd(&g_done, 1u);
        __syncthreads();
        if (rank_sh == gridDim.x - 1) {
            __threadfence();
            const int c = threadIdx.x;
            if (c < DD) {
                float m = colsum[c] / (float)N;
                mu[c] = m;
                colsum[c] = 0.0f;
                s_col[c] = m * m;
            }
            __syncthreads();
            for (int o = 64; o > 0; o >>= 1) {
                if (c < o) s_col[c] += s_col[c + o];
                __syncthreads();
            }
            if (c == 0) {
                float var = fmaxf(sumsq[0] / (float)N - s_col[0], 0.0f);
                invp[0] = 1.0f / (sqrtf(var) + 1e-8f);
                sumsq[0] = 0.0f;
                g_done = 0;
            }
        }
    }
}

// ---------------------------------------------------------------------------
__global__ void k_zero_stats(float* colsum, float* sumsq) {
    int i = threadIdx.x;
    if (i < DD) colsum[i] = 0.0f;
    if (i == 0) { sumsq[0] = 0.0f; g_done = 0; }
}

// ---------------------------------------------------------------------------
extern "C" void kernel_launch(void* const* d_in, const int* in_sizes, int n_in,
                              void* d_out, int out_size) {
    const float* x  = (const float*)d_in[0];
    const int* ei   = (const int*)d_in[1];
    const float* W1 = (const float*)d_in[2];
    const float* W2 = (const float*)d_in[4];
    const float* W3 = (const float*)d_in[6];
    const float* b3 = (const float*)d_in[7];
    float* out = (float*)d_out;

    const int N = in_sizes[0] / DD;
    const int E = in_sizes[1] / 2;
    const int* src = ei;
    const int* dst = ei + E;

    float *p_dinv, *p_colsum, *p_sumsq, *p_mu, *p_inv;
    __half *p_h, *p_agg;
    int *p_degi, *p_incl, *p_bsum, *p_rowptr, *p_cursor, *p_csr;
    cudaGetSymbolAddress((void**)&p_h, g_h);
    cudaGetSymbolAddress((void**)&p_agg, g_agg);
    cudaGetSymbolAddress((void**)&p_degi, g_degi);
    cudaGetSymbolAddress((void**)&p_dinv, g_dinv);
    cudaGetSymbolAddress((void**)&p_incl, g_incl);
    cudaGetSymbolAddress((void**)&p_bsum, g_bsum);
    cudaGetSymbolAddress((void**)&p_rowptr, g_rowptr);
    cudaGetSymbolAddress((void**)&p_cursor, g_cursor);
    cudaGetSymbolAddress((void**)&p_csr, g_csr);
    cudaGetSymbolAddress((void**)&p_colsum, g_colsum);
    cudaGetSymbolAddress((void**)&p_sumsq, g_sumsq);
    cudaGetSymbolAddress((void**)&p_mu, g_mu);
    cudaGetSymbolAddress((void**)&p_inv, g_inv);

    const int SMEM_TC = (2 * 128 * W_STRIDE) * 2; // bytes (W hi+lo only)
    static int inited = 0;
    static cudaStream_t s2;
    static cudaEvent_t evFork, evJoin;
    if (!inited) {
        cudaFuncSetAttribute(k_gemm_tc<float>, cudaFuncAttributeMaxDynamicSharedMemorySize,
                             SMEM_TC);
        cudaFuncSetAttribute(k_gemm_tc<__half>, cudaFuncAttributeMaxDynamicSharedMemorySize,
                             SMEM_TC);
        cudaStreamCreateWithFlags(&s2, cudaStreamNonBlocking);
        cudaEventCreateWithFlags(&evFork, cudaEventDisableTiming);
        cudaEventCreateWithFlags(&evJoin, cudaEventDisableTiming);
        inited = 1;
    }

    const int BT = 256;
    const int nBlkN = (N + BT - 1) / BT;
    const int nBlkE = (E + BT - 1) / BT;
    const int nBlkGemm = (N + 127) / 128;
    const int nScan = (N + 1023) / 1024;
    const int nBlkAgg = 1480;

    // --- degree count (needed by both branches) ---
    cudaMemsetAsync(p_degi, 0, (size_t)N * sizeof(int));
    k_deg_count<<<nBlkE, BT>>>(dst, p_degi, E);
    // fork point: scans depend only on deg_count
    cudaEventRecord(evFork, 0);
    cudaStreamWaitEvent(s2, evFork, 0);

    // main stream continues; launch calls ordered so gemm1 is the 5th kernel
    k_zero_stats<<<1, DD>>>(p_colsum, p_sumsq);
    k_dinv<<<nBlkN, BT>>>(p_degi, p_dinv, N);
    k_gemm_tc<float><<<nBlkGemm, BT, SMEM_TC>>>(x, W1, p_h, p_mu, p_inv, p_dinv, 0, N);

    // CSR build on s2 (graph edges: depends on evFork only — overlaps gemm1)
    k_scan1<<<nScan, 1024, 0, s2>>>(p_degi, p_incl, p_bsum, N);
    k_scan2<<<1, 128, 0, s2>>>(p_bsum, nScan);
    k_scan3<<<nBlkN, BT, 0, s2>>>(p_degi, p_incl, p_bsum, p_rowptr, p_cursor, N);
    k_scatter<<<nBlkE, BT, 0, s2>>>(src, dst, p_cursor, p_csr, E);
    cudaEventRecord(evJoin, s2);

    // --- join: aggregation needs CSR ---
    cudaStreamWaitEvent(0, evJoin, 0);

    // ---- Layer 1 (agg computes mu/inv via fused finalize) ----
    k_aggregate<__half, false, true><<<nBlkAgg, BT>>>(
        p_h, p_rowptr, p_csr, p_dinv, p_agg, nullptr, p_colsum, p_sumsq, p_mu, p_inv, N);

    // ---- Layer 2 (PairNorm+ReLU fused into GEMM X-load) ----
    k_gemm_tc<__half><<<nBlkGemm, BT, SMEM_TC>>>(p_agg, W2, p_h, p_mu, p_inv, p_dinv, 1, N);
    k_aggregate<__half, false, true><<<nBlkAgg, BT>>>(
        p_h, p_rowptr, p_csr, p_dinv, p_agg, nullptr, p_colsum, p_sumsq, p_mu, p_inv, N);

    // ---- Layer 3 (output = agg + b3, directly into d_out, fp32) ----
    k_gemm_tc<__half><<<nBlkGemm, BT, SMEM_TC>>>(p_agg, W3, p_h, p_mu, p_inv, p_dinv, 1, N);
    k_aggregate<float, true, false><<<nBlkAgg, BT>>>(
        p_h, p_rowptr, p_csr, p_dinv, out, b3, nullptr, nullptr, nullptr, nullptr, N);
}